// round 2
// baseline (speedup 1.0000x reference)
#include <cuda_runtime.h>
#include <cuda_fp16.h>
#include <cstdint>

// Problem constants
#define B_  8
#define N_  512
#define M_  32
#define HA  128
#define HB  64
#define C_  256          // 2*HA
#define BN_ROWS 4096     // B*N
#define ROWS 131072      // B*N*M
#define EPS 1e-5f

// ---------------- scratch (__device__ globals; no allocation allowed) ----------------
__device__ float  d_S  [BN_ROWS * C_];    // self projection  [4096][256]  4 MB
__device__ float  d_P2 [BN_ROWS * C_];    // gather projection [4096][256] 4 MB
__device__ __half d_gated[(size_t)ROWS * C_];  // 64 MB fp16 scratch
__device__ float  d_nbr[BN_ROWS * HA];    // nbr_sumed 2 MB
__device__ float  d_stats1[512];          // sum[0:256], sumsq[256:512]
__device__ float  d_stats2[256];          // sum[0:128], sumsq[128:256]

// ---------------- f32x2 packed-math helpers ----------------
__device__ __forceinline__ unsigned long long pack2(float lo, float hi) {
    unsigned long long r;
    asm("mov.b64 %0, {%1, %2};" : "=l"(r) : "f"(lo), "f"(hi));
    return r;
}
__device__ __forceinline__ void unpack2(float& lo, float& hi, unsigned long long v) {
    asm("mov.b64 {%0, %1}, %2;" : "=f"(lo), "=f"(hi) : "l"(v));
}
#define FFMA2(d, a, b, c) \
    asm("fma.rn.f32x2 %0, %1, %2, %3;" : "=l"(d) : "l"(a), "l"(b), "l"(c))
#define FADD2(d, a, b) \
    asm("add.rn.f32x2 %0, %1, %2;" : "=l"(d) : "l"(a), "l"(b))

// =====================================================================
// Kernel A: S = X @ W1^T, P2 = X @ W2^T   (X = atom_emb [4096][128])
// One logical GEMM: out[4096][512], K=128.
//   cc < 256 : W row cc,  k-offset 0    -> d_S
//   cc >= 256: W row cc-256, k-offset 128 -> d_P2
// Block 0 also zeroes the stat accumulators so each graph replay is clean.
// =====================================================================
__global__ __launch_bounds__(256) void kA(const float* __restrict__ X,
                                          const float* __restrict__ W) {
    if (blockIdx.x == 0) {
        int t = threadIdx.x;
        d_stats1[t]       = 0.f;
        d_stats1[t + 256] = 0.f;
        d_stats2[t]       = 0.f;
    }

    __shared__ float As[16][64];
    __shared__ float Bs[16][64];

    const int bx = blockIdx.x & 7;        // col tile (0..7)
    const int by = blockIdx.x >> 3;       // row tile (0..63)
    const int row0 = by * 64;
    const int col0 = bx * 64;

    const int tr = threadIdx.x >> 4;      // 0..15
    const int tc = threadIdx.x & 15;      // 0..15

    const int lr  = threadIdx.x >> 2;          // 0..63
    const int lk4 = (threadIdx.x & 3) * 4;     // 0,4,8,12

    const int cc    = col0 + lr;
    const int wrow  = (cc < 256) ? cc : (cc - 256);
    const int woff  = (cc < 256) ? 0  : 128;

    float acc[4][4];
#pragma unroll
    for (int i = 0; i < 4; i++)
#pragma unroll
        for (int j = 0; j < 4; j++) acc[i][j] = 0.f;

    for (int k0 = 0; k0 < 128; k0 += 16) {
        float4 a = *(const float4*)&X[(row0 + lr) * 128 + k0 + lk4];
        As[lk4 + 0][lr] = a.x; As[lk4 + 1][lr] = a.y;
        As[lk4 + 2][lr] = a.z; As[lk4 + 3][lr] = a.w;

        float4 bq = *(const float4*)&W[wrow * 320 + woff + k0 + lk4];
        Bs[lk4 + 0][lr] = bq.x; Bs[lk4 + 1][lr] = bq.y;
        Bs[lk4 + 2][lr] = bq.z; Bs[lk4 + 3][lr] = bq.w;

        __syncthreads();
#pragma unroll
        for (int k = 0; k < 16; k++) {
            float4 av = *(const float4*)&As[k][tr * 4];
            float4 bv = *(const float4*)&Bs[k][tc * 4];
            float ar[4] = {av.x, av.y, av.z, av.w};
            float br[4] = {bv.x, bv.y, bv.z, bv.w};
#pragma unroll
            for (int i = 0; i < 4; i++)
#pragma unroll
                for (int j = 0; j < 4; j++)
                    acc[i][j] = fmaf(ar[i], br[j], acc[i][j]);
        }
        __syncthreads();
    }

#pragma unroll
    for (int i = 0; i < 4; i++) {
        const int r = row0 + tr * 4 + i;
#pragma unroll
        for (int j = 0; j < 4; j++) {
            const int c = col0 + tc * 4 + j;
            if (c < 256) d_S [r * 256 + c]       = acc[i][j];
            else         d_P2[r * 256 + (c-256)] = acc[i][j];
        }
    }
}

// =====================================================================
// Kernel B: per (b,n) CTA (4096 CTAs, 128 threads).
// Thread j owns channel pair (j, j+128).
//   gated = S + mask*P2[adj] + nbr_emb @ W3^T + bias
// E-GEMM inner loop in packed fma.rn.f32x2: weights packed (w_j, w_{j+128}),
// x duplicated in both lanes in SMEM (no per-iteration packing).
// Stores gated as fp16, accumulates fp32 channel sum/sumsq -> global atomics.
// =====================================================================
__global__ __launch_bounds__(128) void kB(const float* __restrict__ nbr_emb,
                                          const int* __restrict__ adj,
                                          const float* __restrict__ mask,
                                          const float* __restrict__ W,
                                          const float* __restrict__ bvec) {
    const int bn = blockIdx.x;               // 0..4095
    const int b  = bn >> 9;
    const int j  = threadIdx.x;              // 0..127

    __shared__ __align__(16) float2 xdup[32][64];   // 16 KB: (x,x) duplicated
    __shared__ int   s_adj[32];
    __shared__ float s_mask[32];

    // cooperative load of this node's 32 neighbor-edge vectors (duplicated)
    const float* xe = nbr_emb + (size_t)bn * 2048;
#pragma unroll
    for (int i = j; i < 2048; i += 128) {
        float v = xe[i];
        xdup[i >> 6][i & 63] = make_float2(v, v);
    }
    if (j < 32) {
        s_adj[j]  = adj[bn * 32 + j];
        s_mask[j] = mask[bn * 32 + j];
    }

    // pack weights for channels (j, j+128), K-slice 256..319
    unsigned long long wp[64];
    const float* w0 = W + j * 320 + 256;
    const float* w1 = W + (j + 128) * 320 + 256;
#pragma unroll
    for (int k = 0; k < 64; k += 4) {
        float4 wa = *(const float4*)(w0 + k);
        float4 wb = *(const float4*)(w1 + k);
        wp[k + 0] = pack2(wa.x, wb.x);
        wp[k + 1] = pack2(wa.y, wb.y);
        wp[k + 2] = pack2(wa.z, wb.z);
        wp[k + 3] = pack2(wa.w, wb.w);
    }

    const float s0 = d_S[bn * 256 + j];
    const float s1 = d_S[bn * 256 + j + 128];
    const float bias0 = bvec[j];
    const float bias1 = bvec[j + 128];

    float sum0 = 0.f, sq0 = 0.f, sum1 = 0.f, sq1 = 0.f;
    __syncthreads();

    __half* grow = d_gated + (size_t)bn * 32 * 256;

#pragma unroll 2
    for (int m = 0; m < 32; m++) {
        unsigned long long a0 = 0ull, a1 = 0ull, a2 = 0ull, a3 = 0ull;
        const ulonglong2* xr = reinterpret_cast<const ulonglong2*>(xdup[m]);
#pragma unroll
        for (int i = 0; i < 32; i += 2) {
            ulonglong2 x0 = xr[i];
            ulonglong2 x1 = xr[i + 1];
            FFMA2(a0, wp[2 * i + 0], x0.x, a0);
            FFMA2(a1, wp[2 * i + 1], x0.y, a1);
            FFMA2(a2, wp[2 * i + 2], x1.x, a2);
            FFMA2(a3, wp[2 * i + 3], x1.y, a3);
        }
        unsigned long long t01, t23, tt;
        FADD2(t01, a0, a1);
        FADD2(t23, a2, a3);
        FADD2(tt, t01, t23);
        float e0, e1;
        unpack2(e0, e1, tt);

        const float mk = s_mask[m];
        const float* p2r = d_P2 + ((size_t)b * 512 + s_adj[m]) * 256;
        const float p0 = p2r[j];
        const float p1 = p2r[j + 128];

        const float g0 = fmaf(mk, p0, e0 + s0 + bias0);
        const float g1 = fmaf(mk, p1, e1 + s1 + bias1);

        sum0 += g0; sq0 = fmaf(g0, g0, sq0);
        sum1 += g1; sq1 = fmaf(g1, g1, sq1);

        grow[m * 256 + j]       = __float2half(g0);
        grow[m * 256 + j + 128] = __float2half(g1);
    }

    atomicAdd(&d_stats1[j],           sum0);
    atomicAdd(&d_stats1[j + 128],     sum1);
    atomicAdd(&d_stats1[256 + j],       sq0);
    atomicAdd(&d_stats1[256 + j + 128], sq1);
}

// =====================================================================
// Kernel D: BN1 affine + sigmoid(filter)*relu(core), summed over M
// -> d_nbr [4096][128]
// =====================================================================
__global__ __launch_bounds__(128) void kD(const float* __restrict__ gamma_h,
                                          const float* __restrict__ beta_h) {
    const int bn = blockIdx.x;
    const int j  = threadIdx.x;
    const float inv = 1.f / (float)ROWS;

    float mean0 = d_stats1[j] * inv;
    float var0  = d_stats1[256 + j] * inv - mean0 * mean0;
    float sc0   = gamma_h[j] * rsqrtf(var0 + EPS);
    float sh0   = beta_h[j] - mean0 * sc0;

    float mean1 = d_stats1[j + 128] * inv;
    float var1  = d_stats1[256 + j + 128] * inv - mean1 * mean1;
    float sc1   = gamma_h[j + 128] * rsqrtf(var1 + EPS);
    float sh1   = beta_h[j + 128] - mean1 * sc1;

    const __half* grow = d_gated + (size_t)bn * 32 * 256;
    float acc = 0.f;
#pragma unroll
    for (int m = 0; m < 32; m++) {
        float f = fmaf(__half2float(grow[m * 256 + j]),       sc0, sh0);
        float g = fmaf(__half2float(grow[m * 256 + j + 128]), sc1, sh1);
        float sig = 1.f / (1.f + __expf(-f));
        acc = fmaf(sig, fmaxf(g, 0.f), acc);
    }
    d_nbr[bn * 128 + j] = acc;
}

// =====================================================================
// Kernel E: BN2 stats (sum/sumsq per 128 channels over 4096 rows)
// =====================================================================
__global__ __launch_bounds__(128) void kE() {
    const int j  = threadIdx.x;
    const int r0 = blockIdx.x * 128;
    float s = 0.f, ss = 0.f;
#pragma unroll 4
    for (int r = r0; r < r0 + 128; r++) {
        float v = d_nbr[r * 128 + j];
        s += v;
        ss = fmaf(v, v, ss);
    }
    atomicAdd(&d_stats2[j],       s);
    atomicAdd(&d_stats2[128 + j], ss);
}

// =====================================================================
// Kernel F: out = relu(atom_emb + BN2(nbr_sumed))
// =====================================================================
__global__ __launch_bounds__(128) void kF(const float* __restrict__ atom_emb,
                                          const float* __restrict__ gamma_o,
                                          const float* __restrict__ beta_o,
                                          float* __restrict__ out) {
    const int bn = blockIdx.x;
    const int j  = threadIdx.x;
    const float inv = 1.f / (float)BN_ROWS;

    float mean = d_stats2[j] * inv;
    float var  = d_stats2[128 + j] * inv - mean * mean;
    float sc   = gamma_o[j] * rsqrtf(var + EPS);
    float sh   = beta_o[j] - mean * sc;

    float v = atom_emb[bn * 128 + j] + fmaf(d_nbr[bn * 128 + j], sc, sh);
    out[bn * 128 + j] = fmaxf(v, 0.f);
}

// =====================================================================
extern "C" void kernel_launch(void* const* d_in, const int* in_sizes, int n_in,
                              void* d_out, int out_size) {
    (void)in_sizes; (void)n_in; (void)out_size;
    const float* atom_emb = (const float*)d_in[0];
    const float* nbr_emb  = (const float*)d_in[1];
    const int*   adj      = (const int*)d_in[2];   // jax int64 request -> int32 (x64 disabled)
    const float* mask     = (const float*)d_in[3];
    const float* W        = (const float*)d_in[4];
    const float* bvec     = (const float*)d_in[5];
    const float* gamma_h  = (const float*)d_in[6];
    const float* beta_h   = (const float*)d_in[7];
    const float* gamma_o  = (const float*)d_in[8];
    const float* beta_o   = (const float*)d_in[9];
    float* out = (float*)d_out;

    kA<<<512,  256>>>(atom_emb, W);
    kB<<<4096, 128>>>(nbr_emb, adj, mask, W, bvec);
    kD<<<4096, 128>>>(gamma_h, beta_h);
    kE<<<32,   128>>>();
    kF<<<4096, 128>>>(atom_emb, gamma_o, beta_o, out);
}